// round 15
// baseline (speedup 1.0000x reference)
#include <cuda_runtime.h>
#include <cuda_bf16.h>
#include <math.h>

#define B_SZ 32
#define C_SZ 64
#define T_SZ 8192
#define KSPLIT 4
#define NCH 64               // 32-sample k-chunks per CTA (8192/4 splits/32)
#define NSTG 4
#define STG_B 16384          // per stage: hi tile 8KB + lo tile 8KB
#define GRAM_SMEM (NSTG * STG_B)

// ---------------- scratch (static device globals; no allocation) ----------------
__device__ __nv_bfloat16 g_Zhi[(size_t)B_SZ * 64 * 2 * 8192];   // 67 MB
__device__ __nv_bfloat16 g_Zlo[(size_t)B_SZ * 64 * 2 * 8192];   // 67 MB
// partials per (split,b): rows 0-63 hh, 64-127 hl, 128-191 hl^T, 192-255 R, 256-319 R^T
__device__ float  g_G2[(size_t)KSPLIT * B_SZ * 320 * 64];       // 10.5 MB
__device__ float2 g_tw[T_SZ / 2];
__device__ float  g_F1[64 * 128];                               // EE @ w1 (batch-invariant)
// tail inter-kernel scratch
__device__ float  g_t2s [(size_t)B_SZ * 4096];
__device__ float  g_qs  [(size_t)B_SZ * 4096];
__device__ float  g_ks  [(size_t)B_SZ * 4096];
__device__ float  g_vs  [(size_t)B_SZ * 4096];

__device__ __forceinline__ float2 cmul(float2 a, float2 b) {
    return make_float2(a.x * b.x - a.y * b.y, a.x * b.y + a.y * b.x);
}
__device__ __forceinline__ float2 cadd(float2 a, float2 b) { return make_float2(a.x + b.x, a.y + b.y); }
__device__ __forceinline__ float2 csub(float2 a, float2 b) { return make_float2(a.x - b.x, a.y - b.y); }
__device__ __forceinline__ float2 cmulc(float2 v, float cx, float cy) {
    return make_float2(v.x * cx - v.y * cy, v.x * cy + v.y * cx);
}
__device__ __forceinline__ int SW(int i) { return i ^ ((i >> 5) & 31); }

__device__ __forceinline__ unsigned smem_u32(const void* p) {
    unsigned a;
    asm("{ .reg .u64 t; cvta.to.shared.u64 t, %1; cvt.u32.u64 %0, t; }" : "=r"(a) : "l"(p));
    return a;
}
__device__ __forceinline__ void cpasync16(unsigned dst, const void* src) {
    asm volatile("cp.async.cg.shared.global [%0], [%1], 16;" :: "r"(dst), "l"(src) : "memory");
}
__device__ __forceinline__ void ldsm4(unsigned& r0, unsigned& r1, unsigned& r2, unsigned& r3,
                                      unsigned addr) {
    asm volatile("ldmatrix.sync.aligned.m8n8.x4.shared.b16 {%0,%1,%2,%3}, [%4];"
                 : "=r"(r0), "=r"(r1), "=r"(r2), "=r"(r3) : "r"(addr));
}
__device__ __forceinline__ void mma16816(float* c, unsigned a0, unsigned a1, unsigned a2,
                                         unsigned a3, unsigned b0, unsigned b1) {
    asm volatile("mma.sync.aligned.m16n8k16.row.col.f32.bf16.bf16.f32 "
                 "{%0,%1,%2,%3}, {%4,%5,%6,%7}, {%8,%9}, {%0,%1,%2,%3};"
                 : "+f"(c[0]), "+f"(c[1]), "+f"(c[2]), "+f"(c[3])
                 : "r"(a0), "r"(a1), "r"(a2), "r"(a3), "r"(b0), "r"(b1));
}

#define RC8 0.70710678118654752f
#define C16 0.92387953251128676f
#define S16 0.38268343236508977f

// ---- radix-16 forward butterfly in registers (DIF stages st..st+3) ----
__device__ __forceinline__ void fft16_fwd_regs(float2* u, float2 W1, float2 W2,
                                               float2 W4, float2 W8) {
    float2 W1k[8];
    W1k[0] = W1;
    W1k[1] = cmulc(W1,  C16, -S16);
    W1k[2] = cmulc(W1,  RC8, -RC8);
    W1k[3] = cmulc(W1,  S16, -C16);
    W1k[4] = make_float2(W1.y, -W1.x);
    W1k[5] = cmulc(W1, -S16, -C16);
    W1k[6] = cmulc(W1, -RC8, -RC8);
    W1k[7] = cmulc(W1, -C16, -S16);
    #pragma unroll
    for (int k = 0; k < 8; k++) {
        float2 sum = cadd(u[k], u[k + 8]);
        float2 dif = csub(u[k], u[k + 8]);
        u[k] = sum;
        u[k + 8] = cmul(dif, W1k[k]);
    }
    float2 W2k[4];
    W2k[0] = W2;
    W2k[1] = cmulc(W2,  RC8, -RC8);
    W2k[2] = make_float2(W2.y, -W2.x);
    W2k[3] = cmulc(W2, -RC8, -RC8);
    #pragma unroll
    for (int g = 0; g < 16; g += 8)
        #pragma unroll
        for (int k = 0; k < 4; k++) {
            float2 sum = cadd(u[g + k], u[g + k + 4]);
            float2 dif = csub(u[g + k], u[g + k + 4]);
            u[g + k] = sum;
            u[g + k + 4] = cmul(dif, W2k[k]);
        }
    float2 W4k[2] = { W4, make_float2(W4.y, -W4.x) };
    #pragma unroll
    for (int g = 0; g < 16; g += 4)
        #pragma unroll
        for (int k = 0; k < 2; k++) {
            float2 sum = cadd(u[g + k], u[g + k + 2]);
            float2 dif = csub(u[g + k], u[g + k + 2]);
            u[g + k] = sum;
            u[g + k + 2] = cmul(dif, W4k[k]);
        }
    #pragma unroll
    for (int g = 0; g < 16; g += 2) {
        float2 sum = cadd(u[g], u[g + 1]);
        float2 dif = csub(u[g], u[g + 1]);
        u[g] = sum;
        u[g + 1] = cmul(dif, W8);
    }
}

// ---- radix-16 inverse butterfly in registers (DIT stages st..st+3) ----
__device__ __forceinline__ void fft16_inv_regs(float2* u, float2 W1, float2 W2,
                                               float2 W4, float2 W8) {
    #pragma unroll
    for (int g = 0; g < 16; g += 2) {
        float2 v = cmul(u[g + 1], W1);
        float2 t = u[g];
        u[g]     = cadd(t, v);
        u[g + 1] = csub(t, v);
    }
    float2 W2k[2] = { W2, make_float2(-W2.y, W2.x) };
    #pragma unroll
    for (int g = 0; g < 16; g += 4)
        #pragma unroll
        for (int k = 0; k < 2; k++) {
            float2 v = cmul(u[g + k + 2], W2k[k]);
            float2 t = u[g + k];
            u[g + k]     = cadd(t, v);
            u[g + k + 2] = csub(t, v);
        }
    float2 W4k[4];
    W4k[0] = W4;
    W4k[1] = cmulc(W4,  RC8, RC8);
    W4k[2] = make_float2(-W4.y, W4.x);
    W4k[3] = cmulc(W4, -RC8, RC8);
    #pragma unroll
    for (int g = 0; g < 16; g += 8)
        #pragma unroll
        for (int k = 0; k < 4; k++) {
            float2 v = cmul(u[g + k + 4], W4k[k]);
            float2 t = u[g + k];
            u[g + k]     = cadd(t, v);
            u[g + k + 4] = csub(t, v);
        }
    float2 W8k[8];
    W8k[0] = W8;
    W8k[1] = cmulc(W8,  C16, S16);
    W8k[2] = cmulc(W8,  RC8, RC8);
    W8k[3] = cmulc(W8,  S16, C16);
    W8k[4] = make_float2(-W8.y, W8.x);
    W8k[5] = cmulc(W8, -S16, C16);
    W8k[6] = cmulc(W8, -RC8, RC8);
    W8k[7] = cmulc(W8, -C16, S16);
    #pragma unroll
    for (int k = 0; k < 8; k++) {
        float2 v = cmul(u[k + 8], W8k[k]);
        float2 t = u[k];
        u[k]     = cadd(t, v);
        u[k + 8] = csub(t, v);
    }
}

// ---------------- init: twiddles (blocks 0-15) + F1 = EE @ w1 (blocks 16-31) ----
__global__ void init_kernel(const float* __restrict__ EE, const float* __restrict__ w1) {
    const int blk = blockIdx.x, tid = threadIdx.x;
    if (blk < 16) {
        int i = blk * 256 + tid;
        if (i < T_SZ / 2) {
            double ang = -2.0 * 3.14159265358979323846 * (double)i / (double)T_SZ;
            g_tw[i] = make_float2((float)cos(ang), (float)sin(ang));
        }
    } else {
        #pragma unroll
        for (int v = 0; v < 2; v++) {
            int idx = (blk - 16) * 512 + v * 256 + tid;
            int r = idx >> 7, f = idx & 127;
            float acc = 0.f;
            #pragma unroll 8
            for (int e = 0; e < 64; e++) acc += EE[r * 64 + e] * w1[e * 128 + f];
            g_F1[idx] = acc;
        }
    }
}

// ---------------- FFT (pair-packed real channels), radix-16 trips ---------------
__global__ __launch_bounds__(512, 2) void fft_hilbert_kernel(const float* __restrict__ x) {
    extern __shared__ float2 s[];   // 64 KB
    const int blk = blockIdx.x;
    const int b = blk >> 5, cp = blk & 31;
    const float* __restrict__ xa = x + ((size_t)b * C_SZ + 2 * cp) * T_SZ;
    const float* __restrict__ xb = xa + T_SZ;
    const int q = threadIdx.x;

    float2 u[16];

    #pragma unroll
    for (int k = 0; k < 16; k++)
        u[k] = make_float2(xa[q + 512 * k], xb[q + 512 * k]);
    fft16_fwd_regs(u, g_tw[q], g_tw[2 * q], g_tw[4 * q], g_tw[8 * q]);
    #pragma unroll
    for (int k = 0; k < 16; k++) s[SW(q + 512 * k)] = u[k];
    __syncthreads();

    {
        const int j0 = q & 31, i = ((q >> 5) << 9) + j0;
        #pragma unroll
        for (int k = 0; k < 16; k++) u[k] = s[SW(i + 32 * k)];
        fft16_fwd_regs(u, g_tw[j0 << 4], g_tw[j0 << 5], g_tw[j0 << 6], g_tw[j0 << 7]);
        __syncthreads();
        #pragma unroll
        for (int k = 0; k < 16; k++) s[SW(i + 32 * k)] = u[k];
    }
    __syncthreads();

    {
        const int j0 = q & 1, i = ((q >> 1) << 5) + j0;
        #pragma unroll
        for (int k = 0; k < 16; k++) u[k] = s[SW(i + 2 * k)];
        fft16_fwd_regs(u, g_tw[j0 << 8], g_tw[j0 << 9], g_tw[j0 << 10], g_tw[j0 << 11]);
        __syncthreads();
        #pragma unroll
        for (int k = 0; k < 16; k++) s[SW(i + 2 * k)] = u[k];
    }
    __syncthreads();

    {
        const int i = q * 16;
        #pragma unroll
        for (int k2 = 0; k2 < 8; k2++) {
            int t = 8 * q + k2;
            float2 a = cadd(s[SW(i + 2 * k2)], s[SW(i + 2 * k2 + 1)]);
            float2 d = csub(s[SW(i + 2 * k2)], s[SW(i + 2 * k2 + 1)]);
            if (t == 0) { u[0] = a; u[1] = d; }
            else {
                u[2 * k2]     = make_float2(2.f * a.x, 2.f * a.y);
                u[2 * k2 + 1] = make_float2(0.f, 0.f);
            }
        }
        const float2 one = make_float2(1.f, 0.f);
        fft16_inv_regs(u, one, one, one, one);
        __syncthreads();
        #pragma unroll
        for (int k = 0; k < 16; k++) s[SW(i + k)] = u[k];
    }
    __syncthreads();

    {
        const int j0 = q & 15, i = ((q >> 4) << 8) + j0;
        #pragma unroll
        for (int k = 0; k < 16; k++) u[k] = s[SW(i + 16 * k)];
        float2 c1 = g_tw[j0 << 8], c2 = g_tw[j0 << 7];
        float2 c4 = g_tw[j0 << 6], c8 = g_tw[j0 << 5];
        fft16_inv_regs(u, make_float2(c1.x, -c1.y), make_float2(c2.x, -c2.y),
                          make_float2(c4.x, -c4.y), make_float2(c8.x, -c8.y));
        __syncthreads();
        #pragma unroll
        for (int k = 0; k < 16; k++) s[SW(i + 16 * k)] = u[k];
    }
    __syncthreads();

    {
        const int j0 = q & 255, i = ((q >> 8) << 12) + j0;
        #pragma unroll
        for (int k = 0; k < 16; k++) u[k] = s[SW(i + 256 * k)];
        float2 c1 = g_tw[j0 << 4], c2 = g_tw[j0 << 3];
        float2 c4 = g_tw[j0 << 2], c8 = g_tw[j0 << 1];
        fft16_inv_regs(u, make_float2(c1.x, -c1.y), make_float2(c2.x, -c2.y),
                          make_float2(c4.x, -c4.y), make_float2(c8.x, -c8.y));
        __syncthreads();
        #pragma unroll
        for (int k = 0; k < 16; k++) s[SW(i + 256 * k)] = u[k];
    }
    __syncthreads();

    const size_t pbase0 = ((size_t)(b * C_SZ + 2 * cp)) * 16384;
    const size_t pbase1 = pbase0 + 16384;
    const float invN = 1.0f / 8192.0f;
    #pragma unroll
    for (int rr = 0; rr < 8; rr++) {
        int t = q + rr * 512;
        float2 tm = g_tw[t];
        float2 w = make_float2(tm.x, -tm.y);
        float2 uu = s[SW(t)];
        float2 v = cmul(s[SW(t + 4096)], w);
        float2 Wv[2] = { cadd(uu, v), csub(uu, v) };
        int ti[2] = { t, t + 4096 };
        #pragma unroll
        for (int e = 0; e < 2; e++) {
            int idx = ti[e];
            float Wr = Wv[e].x * invN, Wi = Wv[e].y * invN;
            float av = xa[idx], bv = xb[idx];
            float zr[2] = { av, bv };
            float zi[2] = { Wi - bv, av - Wr };
            size_t pb[2] = { pbase0, pbase1 };
            #pragma unroll
            for (int ch = 0; ch < 2; ch++) {
                float inv = rsqrtf(zr[ch] * zr[ch] + zi[ch] * zi[ch]);
                float r = zr[ch] * inv, i2 = zi[ch] * inv;
                __nv_bfloat16 rh = __float2bfloat16(r);
                __nv_bfloat16 ih = __float2bfloat16(i2);
                __nv_bfloat16 rl = __float2bfloat16(r - __bfloat162float(rh));
                __nv_bfloat16 il = __float2bfloat16(i2 - __bfloat162float(ih));
                g_Zhi[pb[ch] + idx]        = rh;
                g_Zhi[pb[ch] + 8192 + idx] = ih;
                g_Zlo[pb[ch] + idx]        = rl;
                g_Zlo[pb[ch] + 8192 + idx] = il;
            }
        }
    }
}

// ---------------- gram via HMMA, 7 exact passes; epilogue writes transposes -----
__global__ __launch_bounds__(256) void gram_mma_kernel() {
    extern __shared__ __align__(1024) char gsm[];
    const unsigned sbase = smem_u32(gsm);
    const int split = blockIdx.x, b = blockIdx.y;
    const int tid = threadIdx.x, lane = tid & 31, w = tid >> 5;
    const int mrow = 16 * (w & 3);
    const bool isIm = (w >= 4);

    const char* hi0 = (const char*)g_Zhi + (size_t)b * 64 * 32768 + (size_t)split * 4096;
    const char* lo0 = (const char*)g_Zlo + (size_t)b * 64 * 32768 + (size_t)split * 4096;

    unsigned swo[2]; size_t gofs[2];
    #pragma unroll
    for (int v = 0; v < 2; v++) {
        int u = v * 256 + tid;
        int rw = u >> 3, seg = u & 7;
        unsigned off = rw * 128 + seg * 16;
        swo[v] = off ^ ((off >> 3) & 0x70);
        gofs[v] = (size_t)rw * 32768 + (seg & 3) * 16 + ((seg >= 4) ? 16384 : 0);
    }

    const int lr = lane & 15, lcb = lane >> 4;
    unsigned a_off0 = (mrow + lr) * 128 + lcb * 16;
    unsigned aX = ((a_off0 >> 3) & 0x70);
    unsigned b_off0[4], bX[4];
    #pragma unroll
    for (int q = 0; q < 4; q++) {
        b_off0[q] = (16 * q + lr) * 128 + lcb * 16;
        bX[q] = ((b_off0[q] >> 3) & 0x70);
    }

    float c1[8][4] = {};
    float c2[8][4] = {};

    #pragma unroll
    for (int j = 0; j < 3; j++) {
        unsigned st = sbase + j * STG_B;
        #pragma unroll
        for (int v = 0; v < 2; v++) {
            cpasync16(st + swo[v],        hi0 + gofs[v] + j * 64);
            cpasync16(st + 8192 + swo[v], lo0 + gofs[v] + j * 64);
        }
        asm volatile("cp.async.commit_group;" ::: "memory");
    }

    for (int i = 0; i < NCH; i++) {
        int jn = i + 3;
        if (jn < NCH) {
            unsigned st = sbase + (jn % NSTG) * STG_B;
            #pragma unroll
            for (int v = 0; v < 2; v++) {
                cpasync16(st + swo[v],        hi0 + gofs[v] + (size_t)jn * 64);
                cpasync16(st + 8192 + swo[v], lo0 + gofs[v] + (size_t)jn * 64);
            }
            asm volatile("cp.async.commit_group;" ::: "memory");
            asm volatile("cp.async.wait_group 3;" ::: "memory");
        } else {
            asm volatile("cp.async.wait_group 0;" ::: "memory");
        }
        __syncthreads();

        const unsigned sb = sbase + (i % NSTG) * STG_B;
        if (!isIm) {
            #pragma unroll
            for (int ks = 0; ks < 2; ks++) {
                unsigned ar0, ar1, ar2, ar3, ai0, ai1, ai2, ai3;
                ldsm4(ar0, ar1, ar2, ar3, sb + ((a_off0 + ks * 32) ^ aX));
                ldsm4(ai0, ai1, ai2, ai3, sb + ((a_off0 + 64 + ks * 32) ^ aX));
                #pragma unroll
                for (int q = 0; q < 4; q++) {
                    unsigned rh0, rh1, rh2, rh3, ih0, ih1, ih2, ih3;
                    unsigned rl0, rl1, rl2, rl3, il0, il1, il2, il3;
                    unsigned bar = sb + ((b_off0[q] + ks * 32) ^ bX[q]);
                    unsigned bai = sb + ((b_off0[q] + 64 + ks * 32) ^ bX[q]);
                    ldsm4(rh0, rh1, rh2, rh3, bar);
                    ldsm4(ih0, ih1, ih2, ih3, bai);
                    ldsm4(rl0, rl1, rl2, rl3, bar + 8192);
                    ldsm4(il0, il1, il2, il3, bai + 8192);
                    mma16816(c1[2 * q],     ar0, ar1, ar2, ar3, rh0, rh2);
                    mma16816(c1[2 * q + 1], ar0, ar1, ar2, ar3, rh1, rh3);
                    mma16816(c1[2 * q],     ai0, ai1, ai2, ai3, ih0, ih2);
                    mma16816(c1[2 * q + 1], ai0, ai1, ai2, ai3, ih1, ih3);
                    mma16816(c2[2 * q],     ar0, ar1, ar2, ar3, rl0, rl2);
                    mma16816(c2[2 * q + 1], ar0, ar1, ar2, ar3, rl1, rl3);
                    mma16816(c2[2 * q],     ai0, ai1, ai2, ai3, il0, il2);
                    mma16816(c2[2 * q + 1], ai0, ai1, ai2, ai3, il1, il3);
                }
            }
        } else {
            #pragma unroll
            for (int ks = 0; ks < 2; ks++) {
                unsigned ah0, ah1, ah2, ah3, al0, al1, al2, al3;
                unsigned aai = sb + ((a_off0 + 64 + ks * 32) ^ aX);
                ldsm4(ah0, ah1, ah2, ah3, aai);
                ldsm4(al0, al1, al2, al3, aai + 8192);
                #pragma unroll
                for (int q = 0; q < 4; q++) {
                    unsigned rh0, rh1, rh2, rh3, rl0, rl1, rl2, rl3;
                    unsigned bar = sb + ((b_off0[q] + ks * 32) ^ bX[q]);
                    ldsm4(rh0, rh1, rh2, rh3, bar);
                    ldsm4(rl0, rl1, rl2, rl3, bar + 8192);
                    mma16816(c1[2 * q],     ah0, ah1, ah2, ah3, rh0, rh2);
                    mma16816(c1[2 * q + 1], ah0, ah1, ah2, ah3, rh1, rh3);
                    mma16816(c1[2 * q],     ah0, ah1, ah2, ah3, rl0, rl2);
                    mma16816(c1[2 * q + 1], ah0, ah1, ah2, ah3, rl1, rl3);
                    mma16816(c1[2 * q],     al0, al1, al2, al3, rh0, rh2);
                    mma16816(c1[2 * q + 1], al0, al1, al2, al3, rh1, rh3);
                }
            }
        }
        __syncthreads();
    }

    float* G = g_G2 + ((size_t)(split * B_SZ + b)) * 20480;
    int rr0 = mrow + (lane >> 2);
    if (!isIm) {
        #pragma unroll
        for (int j = 0; j < 8; j++) {
            int col = 8 * j + 2 * (lane & 3);
            G[rr0 * 64 + col]              = c1[j][0];
            G[rr0 * 64 + col + 1]          = c1[j][1];
            G[(rr0 + 8) * 64 + col]        = c1[j][2];
            G[(rr0 + 8) * 64 + col + 1]    = c1[j][3];
            G[(64 + rr0) * 64 + col]         = c2[j][0];
            G[(64 + rr0) * 64 + col + 1]     = c2[j][1];
            G[(64 + rr0 + 8) * 64 + col]     = c2[j][2];
            G[(64 + rr0 + 8) * 64 + col + 1] = c2[j][3];
            G[(128 + col) * 64 + rr0]         = c2[j][0];
            G[(128 + col + 1) * 64 + rr0]     = c2[j][1];
            G[(128 + col) * 64 + rr0 + 8]     = c2[j][2];
            G[(128 + col + 1) * 64 + rr0 + 8] = c2[j][3];
        }
    } else {
        #pragma unroll
        for (int j = 0; j < 8; j++) {
            int col = 8 * j + 2 * (lane & 3);
            G[(192 + rr0) * 64 + col]         = c1[j][0];
            G[(192 + rr0) * 64 + col + 1]     = c1[j][1];
            G[(192 + rr0 + 8) * 64 + col]     = c1[j][2];
            G[(192 + rr0 + 8) * 64 + col + 1] = c1[j][3];
            G[(256 + col) * 64 + rr0]         = c1[j][0];
            G[(256 + col + 1) * 64 + rr0]     = c1[j][1];
            G[(256 + col) * 64 + rr0 + 8]     = c1[j][2];
            G[(256 + col + 1) * 64 + rr0 + 8] = c1[j][3];
        }
    }
}

// ================= tail, split 3 ways: grid (4, B) x 256 threads =================
// T1: conn (all-coalesced partial reads) -> h1 -> t2.
#define T1_F1 1040                 // s_conn [16][65]
#define T1_W2 (T1_F1 + 8448)       // s_F1 [64][132]
#define T1_H1 (T1_W2 + 8192)       // s_w2
#define T1_FLOATS (T1_H1 + 2112)   // s_h1 [16][132]

__global__ __launch_bounds__(256) void tail1_kernel(
    const float* __restrict__ b1, const float* __restrict__ w2, float* __restrict__ out)
{
    extern __shared__ float sm[];
    float* s_conn = sm;
    float* s_F1 = sm + T1_F1;
    float* s_w2 = sm + T1_W2;
    float* s_h1 = sm + T1_H1;
    const int g = blockIdx.x, b = blockIdx.y, tid = threadIdx.x;
    const int r0 = g * 16;

    {
        unsigned dF = smem_u32(sm + T1_F1), dW = smem_u32(sm + T1_W2);
        const uint4* sF = (const uint4*)g_F1;
        const uint4* s2 = (const uint4*)w2;
        #pragma unroll
        for (int v = 0; v < 8; v++) {
            int u = tid + v * 256;
            int r = u >> 5, f4 = u & 31;
            cpasync16(dF + (r * 132 + f4 * 4) * 4, sF + u);
            cpasync16(dW + u * 16, s2 + u);
        }
        asm volatile("cp.async.commit_group;" ::: "memory");
    }

    // conn: Re = hh + hl + hl^T, Im = R - R^T. All rows coalesced from g_G2.
    {
        int lr = tid >> 4, c4 = tid & 15;
        int r = r0 + lr;
        float re4[4] = {}, im4[4] = {};
        #pragma unroll
        for (int sp = 0; sp < KSPLIT; sp++) {
            const float* G = g_G2 + ((size_t)(sp * B_SZ + b)) * 20480;
            float4 a  = *(const float4*)&G[r * 64 + 4 * c4];
            float4 bb = *(const float4*)&G[(64 + r) * 64 + 4 * c4];
            float4 tt = *(const float4*)&G[(128 + r) * 64 + 4 * c4];
            float4 rs = *(const float4*)&G[(192 + r) * 64 + 4 * c4];
            float4 rt = *(const float4*)&G[(256 + r) * 64 + 4 * c4];
            re4[0] += a.x + bb.x + tt.x;  im4[0] += rs.x - rt.x;
            re4[1] += a.y + bb.y + tt.y;  im4[1] += rs.y - rt.y;
            re4[2] += a.z + bb.z + tt.z;  im4[2] += rs.z - rt.z;
            re4[3] += a.w + bb.w + tt.w;  im4[3] += rs.w - rt.w;
        }
        float4 val;
        float* vp = (float*)&val;
        #pragma unroll
        for (int j = 0; j < 4; j++) {
            int col = 4 * c4 + j;
            float v = (r == col) ? 0.f
                    : sqrtf(re4[j] * re4[j] + im4[j] * im4[j]) * (1.f / (float)T_SZ);
            vp[j] = v;
            s_conn[lr * 65 + col] = v;
        }
        *(float4*)&out[(size_t)b * 4096 + r * 64 + 4 * c4] = val;
    }
    asm volatile("cp.async.wait_group 0;" ::: "memory");
    __syncthreads();

    // h1 = relu(conn @ F1 + b1): 512 slots, 2/thread
    {
        const float4* b1v = (const float4*)b1;
        #pragma unroll
        for (int it = 0; it < 2; it++) {
            int slot = tid + it * 256;
            int lr = slot >> 5, f4 = slot & 31;
            float4 acc = b1v[f4];
            #pragma unroll 8
            for (int j = 0; j < 64; j++) {
                float4 w = ((const float4*)&s_F1[j * 132])[f4];
                float cn = s_conn[lr * 65 + j];
                acc.x += cn * w.x; acc.y += cn * w.y; acc.z += cn * w.z; acc.w += cn * w.w;
            }
            acc.x = fmaxf(acc.x, 0.f); acc.y = fmaxf(acc.y, 0.f);
            acc.z = fmaxf(acc.z, 0.f); acc.w = fmaxf(acc.w, 0.f);
            ((float4*)&s_h1[lr * 132])[f4] = acc;
        }
    }
    __syncthreads();

    // t2 = h1 @ w2: 256 slots
    {
        int lr = tid >> 4, e4 = tid & 15;
        float4 acc = make_float4(0.f, 0.f, 0.f, 0.f);
        #pragma unroll 8
        for (int f = 0; f < 128; f++) {
            float4 w = ((const float4*)s_w2)[f * 16 + e4];
            float h = s_h1[lr * 132 + f];
            acc.x += h * w.x; acc.y += h * w.y; acc.z += h * w.z; acc.w += h * w.w;
        }
        *(float4*)&g_t2s[(size_t)b * 4096 + (r0 + lr) * 64 + 4 * e4] = acc;
    }
}

// T2: h2 = conn @ t2 + b2 (out#3) -> qkv = h2 @ Wip^T + bip -> q/k/v scratch.
#define T2_WIP 1088                 // s_conn [16][68]
#define T2_T2  (T2_WIP + 12288)     // wip raw
#define T2_H2  (T2_T2 + 4352)       // s_t2 [64][68]
#define T2_WT  (T2_H2 + 1040)       // s_h2 [16][65]
#define T2_FLOATS (T2_WT + 12544)   // WT [64][196]

__global__ __launch_bounds__(256) void tail2_kernel(
    const float* __restrict__ b2, const float* __restrict__ Wip,
    const float* __restrict__ bip, float* __restrict__ out)
{
    extern __shared__ float sm[];
    float* s_conn = sm;
    float* s_wip  = sm + T2_WIP;
    float* s_t2   = sm + T2_T2;
    float* s_h2   = sm + T2_H2;
    float* s_WT   = sm + T2_WT;
    const int g = blockIdx.x, b = blockIdx.y, tid = threadIdx.x;
    const int r0 = g * 16;

    {
        unsigned dC = smem_u32(sm), dT = smem_u32(sm + T2_T2), dW = smem_u32(sm + T2_WIP);
        const uint4* sC = (const uint4*)(out + (size_t)b * 4096 + r0 * 64);  // conn from out
        const uint4* sT = (const uint4*)(g_t2s + (size_t)b * 4096);
        const uint4* sW = (const uint4*)Wip;
        {
            int u = tid;
            int lr = u >> 4, c4 = u & 15;
            cpasync16(dC + (lr * 68 + 4 * c4) * 4, sC + u);
        }
        #pragma unroll
        for (int v = 0; v < 4; v++) {
            int u = tid + v * 256;
            int j = u >> 4, c4 = u & 15;
            cpasync16(dT + (j * 68 + 4 * c4) * 4, sT + u);
        }
        #pragma unroll
        for (int v = 0; v < 12; v++) {
            int u = tid + v * 256;
            cpasync16(dW + u * 16, sW + u);
        }
        asm volatile("cp.async.commit_group;" ::: "memory");
        asm volatile("cp.async.wait_group 0;" ::: "memory");
    }
    __syncthreads();

    // h2 = conn @ t2 + b2 ; out#3
    {
        const float4* b2v = (const float4*)b2;
        int lr = tid >> 4, e4 = tid & 15;
        float4 acc = b2v[e4];
        #pragma unroll 8
        for (int j = 0; j < 64; j++) {
            float4 t4 = *(const float4*)&s_t2[j * 68 + 4 * e4];
            float cn = s_conn[lr * 68 + j];
            acc.x += cn * t4.x; acc.y += cn * t4.y; acc.z += cn * t4.z; acc.w += cn * t4.w;
        }
        s_h2[lr * 65 + 4 * e4]     = acc.x;
        s_h2[lr * 65 + 4 * e4 + 1] = acc.y;
        s_h2[lr * 65 + 4 * e4 + 2] = acc.z;
        s_h2[lr * 65 + 4 * e4 + 3] = acc.w;
        *(float4*)&out[(size_t)(2 * B_SZ * 4096) + (size_t)b * 4096 + (r0 + lr) * 64 + 4 * e4] = acc;
    }
    __syncthreads();

    // transpose Wip -> WT[e][196]
    #pragma unroll
    for (int it = 0; it < 48; it++) {
        int idx = tid + it * 256;
        int e = idx & 63, m = idx >> 6;
        s_WT[e * 196 + m] = s_wip[m * 64 + e];
    }
    __syncthreads();

    // qkv: 768 slots (16 rows x 48 m4), 3/thread
    {
        const float4* bipv = (const float4*)bip;
        #pragma unroll
        for (int it = 0; it < 3; it++) {
            int slot = tid + it * 256;
            int nl = slot & 15, m4 = slot >> 4;
            float4 acc = bipv[m4];
            #pragma unroll 8
            for (int e = 0; e < 64; e++) {
                float4 w = *(const float4*)&s_WT[e * 196 + 4 * m4];
                float h = s_h2[nl * 65 + e];
                acc.x += h * w.x; acc.y += h * w.y; acc.z += h * w.z; acc.w += h * w.w;
            }
            float* dst = (m4 < 16) ? g_qs : (m4 < 32 ? g_ks : g_vs);
            int c4 = m4 & 15;
            *(float4*)&dst[(size_t)b * 4096 + (r0 + nl) * 64 + 4 * c4] = acc;
        }
    }
}

// T3: attention (full k/v in smem) + out_proj (out#2).
#define T3_V   4352                  // s_k [64][68]
#define T3_Q   (T3_V + 4352)         // s_v [64][68]
#define T3_AO  (T3_Q + 1088)         // s_q [16][68]
#define T3_WOP (T3_AO + 1040)        // s_ao [16][65]
#define T3_FLOATS (T3_WOP + 4096)

__global__ __launch_bounds__(256) void tail3_kernel(
    const float* __restrict__ Wop, const float* __restrict__ bop, float* __restrict__ out)
{
    extern __shared__ float sm[];
    float* s_k  = sm;
    float* s_v  = sm + T3_V;
    float* s_q  = sm + T3_Q;
    float* s_ao = sm + T3_AO;
    float* s_wop = sm + T3_WOP;
    const int g = blockIdx.x, b = blockIdx.y, tid = threadIdx.x;
    const int r0 = g * 16;

    {
        unsigned dK = smem_u32(sm), dV = smem_u32(sm + T3_V);
        unsigned dQ = smem_u32(sm + T3_Q), dW = smem_u32(sm + T3_WOP);
        const uint4* sK = (const uint4*)(g_ks + (size_t)b * 4096);
        const uint4* sV = (const uint4*)(g_vs + (size_t)b * 4096);
        const uint4* sQ = (const uint4*)(g_qs + (size_t)b * 4096 + r0 * 64);
        const uint4* sW = (const uint4*)Wop;
        #pragma unroll
        for (int v = 0; v < 4; v++) {
            int u = tid + v * 256;
            int j = u >> 4, c4 = u & 15;
            cpasync16(dK + (j * 68 + 4 * c4) * 4, sK + u);
            cpasync16(dV + (j * 68 + 4 * c4) * 4, sV + u);
            cpasync16(dW + u * 16, sW + u);
        }
        {
            int u = tid;
            int lr = u >> 4, c4 = u & 15;
            cpasync16(dQ + (lr * 68 + 4 * c4) * 4, sQ + u);
        }
        asm volatile("cp.async.commit_group;" ::: "memory");
        asm volatile("cp.async.wait_group 0;" ::: "memory");
    }
    __syncthreads();

    if (tid < 128) {
        int h = tid >> 4, ql = tid & 15;
        const float inv_sqrt_d = 0.35355339059327373f;
        float4 q0 = *(const float4*)&s_q[ql * 68 + h * 8];
        float4 q1 = *(const float4*)&s_q[ql * 68 + h * 8 + 4];
        float mx = -1e30f;
        for (int k = 0; k < 64; k++) {
            float4 k0 = *(const float4*)&s_k[k * 68 + h * 8];
            float4 k1 = *(const float4*)&s_k[k * 68 + h * 8 + 4];
            float sc = q0.x * k0.x + q0.y * k0.y + q0.z * k0.z + q0.w * k0.w
                     + q1.x * k1.x + q1.y * k1.y + q1.z * k1.z + q1.w * k1.w;
            mx = fmaxf(mx, sc * inv_sqrt_d);
        }
        float denom = 0.f;
        float4 ac0 = make_float4(0.f, 0.f, 0.f, 0.f);
        float4 ac1 = make_float4(0.f, 0.f, 0.f, 0.f);
        for (int k = 0; k < 64; k++) {
            float4 k0 = *(const float4*)&s_k[k * 68 + h * 8];
            float4 k1 = *(const float4*)&s_k[k * 68 + h * 8 + 4];
            float sc = q0.x * k0.x + q0.y * k0.y + q0.z * k0.z + q0.w * k0.w
                     + q1.x * k1.x + q1.y * k1.y + q1.z * k1.z + q1.w * k1.w;
            float p = __expf(sc * inv_sqrt_d - mx);
            denom += p;
            float4 v0 = *(const float4*)&s_v[k * 68 + h * 8];
            float4 v1 = *(const float4*)&s_v[k * 68 + h * 8 + 4];
            ac0.x += p * v0.x; ac0.y += p * v0.y; ac0.z += p * v0.z; ac0.w += p * v0.w;
            ac1.x += p * v1.x; ac1.y += p * v1.y; ac1.z += p * v1.z; ac1.w += p * v1.w;
        }
        float rinv = 1.f / denom;
        s_ao[ql * 65 + h * 8 + 0] = ac0.x * rinv;
        s_ao[ql * 65 + h * 8 + 1] = ac0.y * rinv;
        s_ao[ql * 65 + h * 8 + 2] = ac0.z * rinv;
        s_ao[ql * 65 + h * 8 + 3] = ac0.w * rinv;
        s_ao[ql * 65 + h * 8 + 4] = ac1.x * rinv;
        s_ao[ql * 65 + h * 8 + 5] = ac1.y * rinv;
        s_ao[ql * 65 + h * 8 + 6] = ac1.z * rinv;
        s_ao[ql * 65 + h * 8 + 7] = ac1.w * rinv;
    }
    __syncthreads();

    {
        const float4* bopv = (const float4*)bop;
        int nl = tid >> 4, e4 = tid & 15;
        float4 acc = bopv[e4];
        #pragma unroll 8
        for (int f = 0; f < 64; f++) {
            float av = s_ao[nl * 65 + f];
            acc.x += av * s_wop[(4 * e4 + 0) * 64 + f];
            acc.y += av * s_wop[(4 * e4 + 1) * 64 + f];
            acc.z += av * s_wop[(4 * e4 + 2) * 64 + f];
            acc.w += av * s_wop[(4 * e4 + 3) * 64 + f];
        }
        *(float4*)&out[(size_t)(B_SZ * 4096) + (size_t)b * 4096 + (r0 + nl) * 64 + 4 * e4] = acc;
    }
}

// ---------------- launch ----------------
extern "C" void kernel_launch(void* const* d_in, const int* in_sizes, int n_in,
                              void* d_out, int out_size) {
    const float* x   = (const float*)d_in[0];
    const float* EE  = (const float*)d_in[1];
    const float* w1  = (const float*)d_in[2];
    const float* b1  = (const float*)d_in[3];
    const float* w2  = (const float*)d_in[4];
    const float* b2  = (const float*)d_in[5];
    const float* Wip = (const float*)d_in[6];
    const float* bip = (const float*)d_in[7];
    const float* Wop = (const float*)d_in[8];
    const float* bop = (const float*)d_in[9];
    float* out = (float*)d_out;

    cudaFuncSetAttribute(fft_hilbert_kernel,
                         cudaFuncAttributeMaxDynamicSharedMemorySize, 65536);
    cudaFuncSetAttribute(gram_mma_kernel,
                         cudaFuncAttributeMaxDynamicSharedMemorySize, GRAM_SMEM);
    cudaFuncSetAttribute(tail1_kernel,
                         cudaFuncAttributeMaxDynamicSharedMemorySize, T1_FLOATS * 4);
    cudaFuncSetAttribute(tail2_kernel,
                         cudaFuncAttributeMaxDynamicSharedMemorySize, T2_FLOATS * 4);
    cudaFuncSetAttribute(tail3_kernel,
                         cudaFuncAttributeMaxDynamicSharedMemorySize, T3_FLOATS * 4);

    init_kernel<<<32, 256>>>(EE, w1);
    fft_hilbert_kernel<<<B_SZ * C_SZ / 2, 512, 65536>>>(x);
    gram_mma_kernel<<<dim3(KSPLIT, B_SZ), 256, GRAM_SMEM>>>();
    tail1_kernel<<<dim3(4, B_SZ), 256, T1_FLOATS * 4>>>(b1, w2, out);
    tail2_kernel<<<dim3(4, B_SZ), 256, T2_FLOATS * 4>>>(b2, Wip, bip, out);
    tail3_kernel<<<dim3(4, B_SZ), 256, T3_FLOATS * 4>>>(Wop, bop, out);
}

// round 17
// speedup vs baseline: 1.0158x; 1.0158x over previous
#include <cuda_runtime.h>
#include <cuda_bf16.h>
#include <math.h>

#define B_SZ 32
#define C_SZ 64
#define T_SZ 8192
#define KSPLIT 8
#define NCH 32               // 32-sample k-chunks per CTA (8192/8 splits/32)
#define NSTG 4
#define STG_B 16384          // per stage: hi tile 8KB + lo tile 8KB
#define GRAM_SMEM (NSTG * STG_B)

// ---------------- scratch (static device globals; no allocation) ----------------
__device__ __nv_bfloat16 g_Zhi[(size_t)B_SZ * 64 * 2 * 8192];   // 67 MB
__device__ __nv_bfloat16 g_Zlo[(size_t)B_SZ * 64 * 2 * 8192];   // 67 MB
// partials per (split,b): rows 0-63 hh, 64-127 hl, 128-191 hl^T, 192-255 R, 256-319 R^T
__device__ float  g_G2[(size_t)KSPLIT * B_SZ * 320 * 64];       // 21 MB
__device__ float2 g_tw[T_SZ / 2];
__device__ float  g_F1[64 * 128];                               // EE @ w1 (batch-invariant)
// tail inter-kernel scratch
__device__ float  g_t2s [(size_t)B_SZ * 4096];
__device__ float  g_qs  [(size_t)B_SZ * 4096];
__device__ float  g_ks  [(size_t)B_SZ * 4096];
__device__ float  g_vs  [(size_t)B_SZ * 4096];

__device__ __forceinline__ float2 cmul(float2 a, float2 b) {
    return make_float2(a.x * b.x - a.y * b.y, a.x * b.y + a.y * b.x);
}
__device__ __forceinline__ float2 cadd(float2 a, float2 b) { return make_float2(a.x + b.x, a.y + b.y); }
__device__ __forceinline__ float2 csub(float2 a, float2 b) { return make_float2(a.x - b.x, a.y - b.y); }
__device__ __forceinline__ float2 cmulc(float2 v, float cx, float cy) {
    return make_float2(v.x * cx - v.y * cy, v.x * cy + v.y * cx);
}
__device__ __forceinline__ int SW(int i) { return i ^ ((i >> 5) & 31); }

__device__ __forceinline__ unsigned smem_u32(const void* p) {
    unsigned a;
    asm("{ .reg .u64 t; cvta.to.shared.u64 t, %1; cvt.u32.u64 %0, t; }" : "=r"(a) : "l"(p));
    return a;
}
__device__ __forceinline__ void cpasync16(unsigned dst, const void* src) {
    asm volatile("cp.async.cg.shared.global [%0], [%1], 16;" :: "r"(dst), "l"(src) : "memory");
}
__device__ __forceinline__ void ldsm4(unsigned& r0, unsigned& r1, unsigned& r2, unsigned& r3,
                                      unsigned addr) {
    asm volatile("ldmatrix.sync.aligned.m8n8.x4.shared.b16 {%0,%1,%2,%3}, [%4];"
                 : "=r"(r0), "=r"(r1), "=r"(r2), "=r"(r3) : "r"(addr));
}
__device__ __forceinline__ void mma16816(float* c, unsigned a0, unsigned a1, unsigned a2,
                                         unsigned a3, unsigned b0, unsigned b1) {
    asm volatile("mma.sync.aligned.m16n8k16.row.col.f32.bf16.bf16.f32 "
                 "{%0,%1,%2,%3}, {%4,%5,%6,%7}, {%8,%9}, {%0,%1,%2,%3};"
                 : "+f"(c[0]), "+f"(c[1]), "+f"(c[2]), "+f"(c[3])
                 : "r"(a0), "r"(a1), "r"(a2), "r"(a3), "r"(b0), "r"(b1));
}

#define RC8 0.70710678118654752f
#define C16 0.92387953251128676f
#define S16 0.38268343236508977f

// ---- radix-16 forward butterfly in registers (DIF stages st..st+3) ----
__device__ __forceinline__ void fft16_fwd_regs(float2* u, float2 W1, float2 W2,
                                               float2 W4, float2 W8) {
    float2 W1k[8];
    W1k[0] = W1;
    W1k[1] = cmulc(W1,  C16, -S16);
    W1k[2] = cmulc(W1,  RC8, -RC8);
    W1k[3] = cmulc(W1,  S16, -C16);
    W1k[4] = make_float2(W1.y, -W1.x);
    W1k[5] = cmulc(W1, -S16, -C16);
    W1k[6] = cmulc(W1, -RC8, -RC8);
    W1k[7] = cmulc(W1, -C16, -S16);
    #pragma unroll
    for (int k = 0; k < 8; k++) {
        float2 sum = cadd(u[k], u[k + 8]);
        float2 dif = csub(u[k], u[k + 8]);
        u[k] = sum;
        u[k + 8] = cmul(dif, W1k[k]);
    }
    float2 W2k[4];
    W2k[0] = W2;
    W2k[1] = cmulc(W2,  RC8, -RC8);
    W2k[2] = make_float2(W2.y, -W2.x);
    W2k[3] = cmulc(W2, -RC8, -RC8);
    #pragma unroll
    for (int g = 0; g < 16; g += 8)
        #pragma unroll
        for (int k = 0; k < 4; k++) {
            float2 sum = cadd(u[g + k], u[g + k + 4]);
            float2 dif = csub(u[g + k], u[g + k + 4]);
            u[g + k] = sum;
            u[g + k + 4] = cmul(dif, W2k[k]);
        }
    float2 W4k[2] = { W4, make_float2(W4.y, -W4.x) };
    #pragma unroll
    for (int g = 0; g < 16; g += 4)
        #pragma unroll
        for (int k = 0; k < 2; k++) {
            float2 sum = cadd(u[g + k], u[g + k + 2]);
            float2 dif = csub(u[g + k], u[g + k + 2]);
            u[g + k] = sum;
            u[g + k + 2] = cmul(dif, W4k[k]);
        }
    #pragma unroll
    for (int g = 0; g < 16; g += 2) {
        float2 sum = cadd(u[g], u[g + 1]);
        float2 dif = csub(u[g], u[g + 1]);
        u[g] = sum;
        u[g + 1] = cmul(dif, W8);
    }
}

// ---- radix-16 inverse butterfly in registers (DIT stages st..st+3) ----
__device__ __forceinline__ void fft16_inv_regs(float2* u, float2 W1, float2 W2,
                                               float2 W4, float2 W8) {
    #pragma unroll
    for (int g = 0; g < 16; g += 2) {
        float2 v = cmul(u[g + 1], W1);
        float2 t = u[g];
        u[g]     = cadd(t, v);
        u[g + 1] = csub(t, v);
    }
    float2 W2k[2] = { W2, make_float2(-W2.y, W2.x) };
    #pragma unroll
    for (int g = 0; g < 16; g += 4)
        #pragma unroll
        for (int k = 0; k < 2; k++) {
            float2 v = cmul(u[g + k + 2], W2k[k]);
            float2 t = u[g + k];
            u[g + k]     = cadd(t, v);
            u[g + k + 2] = csub(t, v);
        }
    float2 W4k[4];
    W4k[0] = W4;
    W4k[1] = cmulc(W4,  RC8, RC8);
    W4k[2] = make_float2(-W4.y, W4.x);
    W4k[3] = cmulc(W4, -RC8, RC8);
    #pragma unroll
    for (int g = 0; g < 16; g += 8)
        #pragma unroll
        for (int k = 0; k < 4; k++) {
            float2 v = cmul(u[g + k + 4], W4k[k]);
            float2 t = u[g + k];
            u[g + k]     = cadd(t, v);
            u[g + k + 4] = csub(t, v);
        }
    float2 W8k[8];
    W8k[0] = W8;
    W8k[1] = cmulc(W8,  C16, S16);
    W8k[2] = cmulc(W8,  RC8, RC8);
    W8k[3] = cmulc(W8,  S16, C16);
    W8k[4] = make_float2(-W8.y, W8.x);
    W8k[5] = cmulc(W8, -S16, C16);
    W8k[6] = cmulc(W8, -RC8, RC8);
    W8k[7] = cmulc(W8, -C16, S16);
    #pragma unroll
    for (int k = 0; k < 8; k++) {
        float2 v = cmul(u[k + 8], W8k[k]);
        float2 t = u[k];
        u[k]     = cadd(t, v);
        u[k + 8] = csub(t, v);
    }
}

// ---------------- init: twiddles (blocks 0-15) + F1 = EE @ w1 (blocks 16-31) ----
__global__ void init_kernel(const float* __restrict__ EE, const float* __restrict__ w1) {
    const int blk = blockIdx.x, tid = threadIdx.x;
    if (blk < 16) {
        int i = blk * 256 + tid;
        if (i < T_SZ / 2) {
            double ang = -2.0 * 3.14159265358979323846 * (double)i / (double)T_SZ;
            g_tw[i] = make_float2((float)cos(ang), (float)sin(ang));
        }
    } else {
        #pragma unroll
        for (int v = 0; v < 2; v++) {
            int idx = (blk - 16) * 512 + v * 256 + tid;
            int r = idx >> 7, f = idx & 127;
            float acc = 0.f;
            #pragma unroll 8
            for (int e = 0; e < 64; e++) acc += EE[r * 64 + e] * w1[e * 128 + f];
            g_F1[idx] = acc;
        }
    }
}

// ---------------- FFT (pair-packed real channels), radix-16 trips ---------------
__global__ __launch_bounds__(512, 2) void fft_hilbert_kernel(const float* __restrict__ x) {
    extern __shared__ float2 s[];   // 64 KB
    const int blk = blockIdx.x;
    const int b = blk >> 5, cp = blk & 31;
    const float* __restrict__ xa = x + ((size_t)b * C_SZ + 2 * cp) * T_SZ;
    const float* __restrict__ xb = xa + T_SZ;
    const int q = threadIdx.x;

    float2 u[16];

    #pragma unroll
    for (int k = 0; k < 16; k++)
        u[k] = make_float2(xa[q + 512 * k], xb[q + 512 * k]);
    fft16_fwd_regs(u, g_tw[q], g_tw[2 * q], g_tw[4 * q], g_tw[8 * q]);
    #pragma unroll
    for (int k = 0; k < 16; k++) s[SW(q + 512 * k)] = u[k];
    __syncthreads();

    {
        const int j0 = q & 31, i = ((q >> 5) << 9) + j0;
        #pragma unroll
        for (int k = 0; k < 16; k++) u[k] = s[SW(i + 32 * k)];
        fft16_fwd_regs(u, g_tw[j0 << 4], g_tw[j0 << 5], g_tw[j0 << 6], g_tw[j0 << 7]);
        __syncthreads();
        #pragma unroll
        for (int k = 0; k < 16; k++) s[SW(i + 32 * k)] = u[k];
    }
    __syncthreads();

    {
        const int j0 = q & 1, i = ((q >> 1) << 5) + j0;
        #pragma unroll
        for (int k = 0; k < 16; k++) u[k] = s[SW(i + 2 * k)];
        fft16_fwd_regs(u, g_tw[j0 << 8], g_tw[j0 << 9], g_tw[j0 << 10], g_tw[j0 << 11]);
        __syncthreads();
        #pragma unroll
        for (int k = 0; k < 16; k++) s[SW(i + 2 * k)] = u[k];
    }
    __syncthreads();

    {
        const int i = q * 16;
        #pragma unroll
        for (int k2 = 0; k2 < 8; k2++) {
            int t = 8 * q + k2;
            float2 a = cadd(s[SW(i + 2 * k2)], s[SW(i + 2 * k2 + 1)]);
            float2 d = csub(s[SW(i + 2 * k2)], s[SW(i + 2 * k2 + 1)]);
            if (t == 0) { u[0] = a; u[1] = d; }
            else {
                u[2 * k2]     = make_float2(2.f * a.x, 2.f * a.y);
                u[2 * k2 + 1] = make_float2(0.f, 0.f);
            }
        }
        const float2 one = make_float2(1.f, 0.f);
        fft16_inv_regs(u, one, one, one, one);
        __syncthreads();
        #pragma unroll
        for (int k = 0; k < 16; k++) s[SW(i + k)] = u[k];
    }
    __syncthreads();

    {
        const int j0 = q & 15, i = ((q >> 4) << 8) + j0;
        #pragma unroll
        for (int k = 0; k < 16; k++) u[k] = s[SW(i + 16 * k)];
        float2 c1 = g_tw[j0 << 8], c2 = g_tw[j0 << 7];
        float2 c4 = g_tw[j0 << 6], c8 = g_tw[j0 << 5];
        fft16_inv_regs(u, make_float2(c1.x, -c1.y), make_float2(c2.x, -c2.y),
                          make_float2(c4.x, -c4.y), make_float2(c8.x, -c8.y));
        __syncthreads();
        #pragma unroll
        for (int k = 0; k < 16; k++) s[SW(i + 16 * k)] = u[k];
    }
    __syncthreads();

    {
        const int j0 = q & 255, i = ((q >> 8) << 12) + j0;
        #pragma unroll
        for (int k = 0; k < 16; k++) u[k] = s[SW(i + 256 * k)];
        float2 c1 = g_tw[j0 << 4], c2 = g_tw[j0 << 3];
        float2 c4 = g_tw[j0 << 2], c8 = g_tw[j0 << 1];
        fft16_inv_regs(u, make_float2(c1.x, -c1.y), make_float2(c2.x, -c2.y),
                          make_float2(c4.x, -c4.y), make_float2(c8.x, -c8.y));
        __syncthreads();
        #pragma unroll
        for (int k = 0; k < 16; k++) s[SW(i + 256 * k)] = u[k];
    }
    __syncthreads();

    // final trip: inverse stage 12 + 1/N + unpack + normalize + PACKED plane stores.
    // Thread handles 4 consecutive t. smem reads use per-element SW() (the XOR
    // permutes within 32-blocks, so runs are NOT contiguous — R16 bug); global
    // bf16 outputs per plane still pack into one 8-byte store.
    const size_t pbase0 = ((size_t)(b * C_SZ + 2 * cp)) * 16384;
    const size_t pbase1 = pbase0 + 16384;
    const float invN = 1.0f / 8192.0f;
    #pragma unroll
    for (int rr = 0; rr < 2; rr++) {
        const int tq = 4 * (q + rr * 512);      // 0..4092, multiple of 4
        float2 Wv0[4], Wv1[4];
        #pragma unroll
        for (int k = 0; k < 4; k++) {
            float2 tm = g_tw[tq + k];
            float2 w = make_float2(tm.x, -tm.y);
            float2 uu = s[SW(tq + k)];
            float2 v = cmul(s[SW(tq + 4096 + k)], w);
            Wv0[k] = cadd(uu, v);
            Wv1[k] = csub(uu, v);
        }
        #pragma unroll
        for (int gI = 0; gI < 2; gI++) {
            const int idx0 = tq + gI * 4096;
            const float2* Wp = gI ? Wv1 : Wv0;
            float4 xav = *(const float4*)&xa[idx0];
            float4 xbv = *(const float4*)&xb[idx0];
            const float* xap = (const float*)&xav;
            const float* xbp = (const float*)&xbv;
            #pragma unroll
            for (int ch = 0; ch < 2; ch++) {
                const size_t pb = ch ? pbase1 : pbase0;
                union { __nv_bfloat16 h[4]; uint2 u2; } prh, pih, prl, pil;
                #pragma unroll
                for (int k = 0; k < 4; k++) {
                    float Wr = Wp[k].x * invN, Wi = Wp[k].y * invN;
                    float av = xap[k], bv = xbp[k];
                    float zr = ch ? bv : av;
                    float zi = ch ? (av - Wr) : (Wi - bv);
                    float inv = rsqrtf(zr * zr + zi * zi);
                    float r = zr * inv, i2 = zi * inv;
                    __nv_bfloat16 rh = __float2bfloat16(r);
                    __nv_bfloat16 ih = __float2bfloat16(i2);
                    prh.h[k] = rh;
                    pih.h[k] = ih;
                    prl.h[k] = __float2bfloat16(r - __bfloat162float(rh));
                    pil.h[k] = __float2bfloat16(i2 - __bfloat162float(ih));
                }
                *(uint2*)&g_Zhi[pb + idx0]        = prh.u2;
                *(uint2*)&g_Zhi[pb + 8192 + idx0] = pih.u2;
                *(uint2*)&g_Zlo[pb + idx0]        = prl.u2;
                *(uint2*)&g_Zlo[pb + 8192 + idx0] = pil.u2;
            }
        }
    }
}

// ---------------- gram via HMMA, 7 exact passes; epilogue writes transposes -----
__global__ __launch_bounds__(256) void gram_mma_kernel() {
    extern __shared__ __align__(1024) char gsm[];
    const unsigned sbase = smem_u32(gsm);
    const int split = blockIdx.x, b = blockIdx.y;
    const int tid = threadIdx.x, lane = tid & 31, w = tid >> 5;
    const int mrow = 16 * (w & 3);
    const bool isIm = (w >= 4);

    const char* hi0 = (const char*)g_Zhi + (size_t)b * 64 * 32768 + (size_t)split * 2048;
    const char* lo0 = (const char*)g_Zlo + (size_t)b * 64 * 32768 + (size_t)split * 2048;

    unsigned swo[2]; size_t gofs[2];
    #pragma unroll
    for (int v = 0; v < 2; v++) {
        int u = v * 256 + tid;
        int rw = u >> 3, seg = u & 7;
        unsigned off = rw * 128 + seg * 16;
        swo[v] = off ^ ((off >> 3) & 0x70);
        gofs[v] = (size_t)rw * 32768 + (seg & 3) * 16 + ((seg >= 4) ? 16384 : 0);
    }

    const int lr = lane & 15, lcb = lane >> 4;
    unsigned a_off0 = (mrow + lr) * 128 + lcb * 16;
    unsigned aX = ((a_off0 >> 3) & 0x70);
    unsigned b_off0[4], bX[4];
    #pragma unroll
    for (int q = 0; q < 4; q++) {
        b_off0[q] = (16 * q + lr) * 128 + lcb * 16;
        bX[q] = ((b_off0[q] >> 3) & 0x70);
    }

    float c1[8][4] = {};
    float c2[8][4] = {};

    #pragma unroll
    for (int j = 0; j < 3; j++) {
        unsigned st = sbase + j * STG_B;
        #pragma unroll
        for (int v = 0; v < 2; v++) {
            cpasync16(st + swo[v],        hi0 + gofs[v] + j * 64);
            cpasync16(st + 8192 + swo[v], lo0 + gofs[v] + j * 64);
        }
        asm volatile("cp.async.commit_group;" ::: "memory");
    }

    for (int i = 0; i < NCH; i++) {
        int jn = i + 3;
        if (jn < NCH) {
            unsigned st = sbase + (jn % NSTG) * STG_B;
            #pragma unroll
            for (int v = 0; v < 2; v++) {
                cpasync16(st + swo[v],        hi0 + gofs[v] + (size_t)jn * 64);
                cpasync16(st + 8192 + swo[v], lo0 + gofs[v] + (size_t)jn * 64);
            }
            asm volatile("cp.async.commit_group;" ::: "memory");
            asm volatile("cp.async.wait_group 3;" ::: "memory");
        } else {
            asm volatile("cp.async.wait_group 0;" ::: "memory");
        }
        __syncthreads();

        const unsigned sb = sbase + (i % NSTG) * STG_B;
        if (!isIm) {
            #pragma unroll
            for (int ks = 0; ks < 2; ks++) {
                unsigned ar0, ar1, ar2, ar3, ai0, ai1, ai2, ai3;
                ldsm4(ar0, ar1, ar2, ar3, sb + ((a_off0 + ks * 32) ^ aX));
                ldsm4(ai0, ai1, ai2, ai3, sb + ((a_off0 + 64 + ks * 32) ^ aX));
                #pragma unroll
                for (int q = 0; q < 4; q++) {
                    unsigned rh0, rh1, rh2, rh3, ih0, ih1, ih2, ih3;
                    unsigned rl0, rl1, rl2, rl3, il0, il1, il2, il3;
                    unsigned bar = sb + ((b_off0[q] + ks * 32) ^ bX[q]);
                    unsigned bai = sb + ((b_off0[q] + 64 + ks * 32) ^ bX[q]);
                    ldsm4(rh0, rh1, rh2, rh3, bar);
                    ldsm4(ih0, ih1, ih2, ih3, bai);
                    ldsm4(rl0, rl1, rl2, rl3, bar + 8192);
                    ldsm4(il0, il1, il2, il3, bai + 8192);
                    mma16816(c1[2 * q],     ar0, ar1, ar2, ar3, rh0, rh2);
                    mma16816(c1[2 * q + 1], ar0, ar1, ar2, ar3, rh1, rh3);
                    mma16816(c1[2 * q],     ai0, ai1, ai2, ai3, ih0, ih2);
                    mma16816(c1[2 * q + 1], ai0, ai1, ai2, ai3, ih1, ih3);
                    mma16816(c2[2 * q],     ar0, ar1, ar2, ar3, rl0, rl2);
                    mma16816(c2[2 * q + 1], ar0, ar1, ar2, ar3, rl1, rl3);
                    mma16816(c2[2 * q],     ai0, ai1, ai2, ai3, il0, il2);
                    mma16816(c2[2 * q + 1], ai0, ai1, ai2, ai3, il1, il3);
                }
            }
        } else {
            #pragma unroll
            for (int ks = 0; ks < 2; ks++) {
                unsigned ah0, ah1, ah2, ah3, al0, al1, al2, al3;
                unsigned aai = sb + ((a_off0 + 64 + ks * 32) ^ aX);
                ldsm4(ah0, ah1, ah2, ah3, aai);
                ldsm4(al0, al1, al2, al3, aai + 8192);
                #pragma unroll
                for (int q = 0; q < 4; q++) {
                    unsigned rh0, rh1, rh2, rh3, rl0, rl1, rl2, rl3;
                    unsigned bar = sb + ((b_off0[q] + ks * 32) ^ bX[q]);
                    ldsm4(rh0, rh1, rh2, rh3, bar);
                    ldsm4(rl0, rl1, rl2, rl3, bar + 8192);
                    mma16816(c1[2 * q],     ah0, ah1, ah2, ah3, rh0, rh2);
                    mma16816(c1[2 * q + 1], ah0, ah1, ah2, ah3, rh1, rh3);
                    mma16816(c1[2 * q],     ah0, ah1, ah2, ah3, rl0, rl2);
                    mma16816(c1[2 * q + 1], ah0, ah1, ah2, ah3, rl1, rl3);
                    mma16816(c1[2 * q],     al0, al1, al2, al3, rh0, rh2);
                    mma16816(c1[2 * q + 1], al0, al1, al2, al3, rh1, rh3);
                }
            }
        }
        __syncthreads();
    }

    float* G = g_G2 + ((size_t)(split * B_SZ + b)) * 20480;
    int rr0 = mrow + (lane >> 2);
    if (!isIm) {
        #pragma unroll
        for (int j = 0; j < 8; j++) {
            int col = 8 * j + 2 * (lane & 3);
            G[rr0 * 64 + col]              = c1[j][0];
            G[rr0 * 64 + col + 1]          = c1[j][1];
            G[(rr0 + 8) * 64 + col]        = c1[j][2];
            G[(rr0 + 8) * 64 + col + 1]    = c1[j][3];
            G[(64 + rr0) * 64 + col]         = c2[j][0];
            G[(64 + rr0) * 64 + col + 1]     = c2[j][1];
            G[(64 + rr0 + 8) * 64 + col]     = c2[j][2];
            G[(64 + rr0 + 8) * 64 + col + 1] = c2[j][3];
            G[(128 + col) * 64 + rr0]         = c2[j][0];
            G[(128 + col + 1) * 64 + rr0]     = c2[j][1];
            G[(128 + col) * 64 + rr0 + 8]     = c2[j][2];
            G[(128 + col + 1) * 64 + rr0 + 8] = c2[j][3];
        }
    } else {
        #pragma unroll
        for (int j = 0; j < 8; j++) {
            int col = 8 * j + 2 * (lane & 3);
            G[(192 + rr0) * 64 + col]         = c1[j][0];
            G[(192 + rr0) * 64 + col + 1]     = c1[j][1];
            G[(192 + rr0 + 8) * 64 + col]     = c1[j][2];
            G[(192 + rr0 + 8) * 64 + col + 1] = c1[j][3];
            G[(256 + col) * 64 + rr0]         = c1[j][0];
            G[(256 + col + 1) * 64 + rr0]     = c1[j][1];
            G[(256 + col) * 64 + rr0 + 8]     = c1[j][2];
            G[(256 + col + 1) * 64 + rr0 + 8] = c1[j][3];
        }
    }
}

// ================= tail, split 3 ways: grid (4, B) x 256 threads =================
// T1: conn (all-coalesced partial reads) -> h1 -> t2.
#define T1_F1 1040                 // s_conn [16][65]
#define T1_W2 (T1_F1 + 8448)       // s_F1 [64][132]
#define T1_H1 (T1_W2 + 8192)       // s_w2
#define T1_FLOATS (T1_H1 + 2112)   // s_h1 [16][132]

__global__ __launch_bounds__(256) void tail1_kernel(
    const float* __restrict__ b1, const float* __restrict__ w2, float* __restrict__ out)
{
    extern __shared__ float sm[];
    float* s_conn = sm;
    float* s_F1 = sm + T1_F1;
    float* s_w2 = sm + T1_W2;
    float* s_h1 = sm + T1_H1;
    const int g = blockIdx.x, b = blockIdx.y, tid = threadIdx.x;
    const int r0 = g * 16;

    {
        unsigned dF = smem_u32(sm + T1_F1), dW = smem_u32(sm + T1_W2);
        const uint4* sF = (const uint4*)g_F1;
        const uint4* s2 = (const uint4*)w2;
        #pragma unroll
        for (int v = 0; v < 8; v++) {
            int u = tid + v * 256;
            int r = u >> 5, f4 = u & 31;
            cpasync16(dF + (r * 132 + f4 * 4) * 4, sF + u);
            cpasync16(dW + u * 16, s2 + u);
        }
        asm volatile("cp.async.commit_group;" ::: "memory");
    }

    // conn: Re = hh + hl + hl^T, Im = R - R^T. All rows coalesced from g_G2.
    {
        int lr = tid >> 4, c4 = tid & 15;
        int r = r0 + lr;
        float re4[4] = {}, im4[4] = {};
        #pragma unroll
        for (int sp = 0; sp < KSPLIT; sp++) {
            const float* G = g_G2 + ((size_t)(sp * B_SZ + b)) * 20480;
            float4 a  = *(const float4*)&G[r * 64 + 4 * c4];
            float4 bb = *(const float4*)&G[(64 + r) * 64 + 4 * c4];
            float4 tt = *(const float4*)&G[(128 + r) * 64 + 4 * c4];
            float4 rs = *(const float4*)&G[(192 + r) * 64 + 4 * c4];
            float4 rt = *(const float4*)&G[(256 + r) * 64 + 4 * c4];
            re4[0] += a.x + bb.x + tt.x;  im4[0] += rs.x - rt.x;
            re4[1] += a.y + bb.y + tt.y;  im4[1] += rs.y - rt.y;
            re4[2] += a.z + bb.z + tt.z;  im4[2] += rs.z - rt.z;
            re4[3] += a.w + bb.w + tt.w;  im4[3] += rs.w - rt.w;
        }
        float4 val;
        float* vp = (float*)&val;
        #pragma unroll
        for (int j = 0; j < 4; j++) {
            int col = 4 * c4 + j;
            float v = (r == col) ? 0.f
                    : sqrtf(re4[j] * re4[j] + im4[j] * im4[j]) * (1.f / (float)T_SZ);
            vp[j] = v;
            s_conn[lr * 65 + col] = v;
        }
        *(float4*)&out[(size_t)b * 4096 + r * 64 + 4 * c4] = val;
    }
    asm volatile("cp.async.wait_group 0;" ::: "memory");
    __syncthreads();

    // h1 = relu(conn @ F1 + b1): 512 slots, 2/thread
    {
        const float4* b1v = (const float4*)b1;
        #pragma unroll
        for (int it = 0; it < 2; it++) {
            int slot = tid + it * 256;
            int lr = slot >> 5, f4 = slot & 31;
            float4 acc = b1v[f4];
            #pragma unroll 8
            for (int j = 0; j < 64; j++) {
                float4 w = ((const float4*)&s_F1[j * 132])[f4];
                float cn = s_conn[lr * 65 + j];
                acc.x += cn * w.x; acc.y += cn * w.y; acc.z += cn * w.z; acc.w += cn * w.w;
            }
            acc.x = fmaxf(acc.x, 0.f); acc.y = fmaxf(acc.y, 0.f);
            acc.z = fmaxf(acc.z, 0.f); acc.w = fmaxf(acc.w, 0.f);
            ((float4*)&s_h1[lr * 132])[f4] = acc;
        }
    }
    __syncthreads();

    // t2 = h1 @ w2: 256 slots
    {
        int lr = tid >> 4, e4 = tid & 15;
        float4 acc = make_float4(0.f, 0.f, 0.f, 0.f);
        #pragma unroll 8
        for (int f = 0; f < 128; f++) {
            float4 w = ((const float4*)s_w2)[f * 16 + e4];
            float h = s_h1[lr * 132 + f];
            acc.x += h * w.x; acc.y += h * w.y; acc.z += h * w.z; acc.w += h * w.w;
        }
        *(float4*)&g_t2s[(size_t)b * 4096 + (r0 + lr) * 64 + 4 * e4] = acc;
    }
}

// T2: h2 = conn @ t2 + b2 (out#3) -> qkv = h2 @ Wip^T + bip -> q/k/v scratch.
#define T2_WIP 1088                 // s_conn [16][68]
#define T2_T2  (T2_WIP + 12288)     // wip raw
#define T2_H2  (T2_T2 + 4352)       // s_t2 [64][68]
#define T2_WT  (T2_H2 + 1040)       // s_h2 [16][65]
#define T2_FLOATS (T2_WT + 12544)   // WT [64][196]

__global__ __launch_bounds__(256) void tail2_kernel(
    const float* __restrict__ b2, const float* __restrict__ Wip,
    const float* __restrict__ bip, float* __restrict__ out)
{
    extern __shared__ float sm[];
    float* s_conn = sm;
    float* s_wip  = sm + T2_WIP;
    float* s_t2   = sm + T2_T2;
    float* s_h2   = sm + T2_H2;
    float* s_WT   = sm + T2_WT;
    const int g = blockIdx.x, b = blockIdx.y, tid = threadIdx.x;
    const int r0 = g * 16;

    {
        unsigned dC = smem_u32(sm), dT = smem_u32(sm + T2_T2), dW = smem_u32(sm + T2_WIP);
        const uint4* sC = (const uint4*)(out + (size_t)b * 4096 + r0 * 64);  // conn from out
        const uint4* sT = (const uint4*)(g_t2s + (size_t)b * 4096);
        const uint4* sW = (const uint4*)Wip;
        {
            int u = tid;
            int lr = u >> 4, c4 = u & 15;
            cpasync16(dC + (lr * 68 + 4 * c4) * 4, sC + u);
        }
        #pragma unroll
        for (int v = 0; v < 4; v++) {
            int u = tid + v * 256;
            int j = u >> 4, c4 = u & 15;
            cpasync16(dT + (j * 68 + 4 * c4) * 4, sT + u);
        }
        #pragma unroll
        for (int v = 0; v < 12; v++) {
            int u = tid + v * 256;
            cpasync16(dW + u * 16, sW + u);
        }
        asm volatile("cp.async.commit_group;" ::: "memory");
        asm volatile("cp.async.wait_group 0;" ::: "memory");
    }
    __syncthreads();

    // h2 = conn @ t2 + b2 ; out#3
    {
        const float4* b2v = (const float4*)b2;
        int lr = tid >> 4, e4 = tid & 15;
        float4 acc = b2v[e4];
        #pragma unroll 8
        for (int j = 0; j < 64; j++) {
            float4 t4 = *(const float4*)&s_t2[j * 68 + 4 * e4];
            float cn = s_conn[lr * 68 + j];
            acc.x += cn * t4.x; acc.y += cn * t4.y; acc.z += cn * t4.z; acc.w += cn * t4.w;
        }
        s_h2[lr * 65 + 4 * e4]     = acc.x;
        s_h2[lr * 65 + 4 * e4 + 1] = acc.y;
        s_h2[lr * 65 + 4 * e4 + 2] = acc.z;
        s_h2[lr * 65 + 4 * e4 + 3] = acc.w;
        *(float4*)&out[(size_t)(2 * B_SZ * 4096) + (size_t)b * 4096 + (r0 + lr) * 64 + 4 * e4] = acc;
    }
    __syncthreads();

    // transpose Wip -> WT[e][196]
    #pragma unroll
    for (int it = 0; it < 48; it++) {
        int idx = tid + it * 256;
        int e = idx & 63, m = idx >> 6;
        s_WT[e * 196 + m] = s_wip[m * 64 + e];
    }
    __syncthreads();

    // qkv: 768 slots (16 rows x 48 m4), 3/thread
    {
        const float4* bipv = (const float4*)bip;
        #pragma unroll
        for (int it = 0; it < 3; it++) {
            int slot = tid + it * 256;
            int nl = slot & 15, m4 = slot >> 4;
            float4 acc = bipv[m4];
            #pragma unroll 8
            for (int e = 0; e < 64; e++) {
                float4 w = *(const float4*)&s_WT[e * 196 + 4 * m4];
                float h = s_h2[nl * 65 + e];
                acc.x += h * w.x; acc.y += h * w.y; acc.z += h * w.z; acc.w += h * w.w;
            }
            float* dst = (m4 < 16) ? g_qs : (m4 < 32 ? g_ks : g_vs);
            int c4 = m4 & 15;
            *(float4*)&dst[(size_t)b * 4096 + (r0 + nl) * 64 + 4 * c4] = acc;
        }
    }
}

// T3: attention (full k/v in smem) + out_proj (out#2).
#define T3_V   4352                  // s_k [64][68]
#define T3_Q   (T3_V + 4352)         // s_v [64][68]
#define T3_AO  (T3_Q + 1088)         // s_q [16][68]
#define T3_WOP (T3_AO + 1040)        // s_ao [16][65]
#define T3_FLOATS (T3_WOP + 4096)

__global__ __launch_bounds__(256) void tail3_kernel(
    const float* __restrict__ Wop, const float* __restrict__ bop, float* __restrict__ out)
{
    extern __shared__ float sm[];
    float* s_k  = sm;
    float* s_v  = sm + T3_V;
    float* s_q  = sm + T3_Q;
    float* s_ao = sm + T3_AO;
    float* s_wop = sm + T3_WOP;
    const int g = blockIdx.x, b = blockIdx.y, tid = threadIdx.x;
    const int r0 = g * 16;

    {
        unsigned dK = smem_u32(sm), dV = smem_u32(sm + T3_V);
        unsigned dQ = smem_u32(sm + T3_Q), dW = smem_u32(sm + T3_WOP);
        const uint4* sK = (const uint4*)(g_ks + (size_t)b * 4096);
        const uint4* sV = (const uint4*)(g_vs + (size_t)b * 4096);
        const uint4* sQ = (const uint4*)(g_qs + (size_t)b * 4096 + r0 * 64);
        const uint4* sW = (const uint4*)Wop;
        #pragma unroll
        for (int v = 0; v < 4; v++) {
            int u = tid + v * 256;
            int j = u >> 4, c4 = u & 15;
            cpasync16(dK + (j * 68 + 4 * c4) * 4, sK + u);
            cpasync16(dV + (j * 68 + 4 * c4) * 4, sV + u);
            cpasync16(dW + u * 16, sW + u);
        }
        {
            int u = tid;
            int lr = u >> 4, c4 = u & 15;
            cpasync16(dQ + (lr * 68 + 4 * c4) * 4, sQ + u);
        }
        asm volatile("cp.async.commit_group;" ::: "memory");
        asm volatile("cp.async.wait_group 0;" ::: "memory");
    }
    __syncthreads();

    if (tid < 128) {
        int h = tid >> 4, ql = tid & 15;
        const float inv_sqrt_d = 0.35355339059327373f;
        float4 q0 = *(const float4*)&s_q[ql * 68 + h * 8];
        float4 q1 = *(const float4*)&s_q[ql * 68 + h * 8 + 4];
        float mx = -1e30f;
        for (int k = 0; k < 64; k++) {
            float4 k0 = *(const float4*)&s_k[k * 68 + h * 8];
            float4 k1 = *(const float4*)&s_k[k * 68 + h * 8 + 4];
            float sc = q0.x * k0.x + q0.y * k0.y + q0.z * k0.z + q0.w * k0.w
                     + q1.x * k1.x + q1.y * k1.y + q1.z * k1.z + q1.w * k1.w;
            mx = fmaxf(mx, sc * inv_sqrt_d);
        }
        float denom = 0.f;
        float4 ac0 = make_float4(0.f, 0.f, 0.f, 0.f);
        float4 ac1 = make_float4(0.f, 0.f, 0.f, 0.f);
        for (int k = 0; k < 64; k++) {
            float4 k0 = *(const float4*)&s_k[k * 68 + h * 8];
            float4 k1 = *(const float4*)&s_k[k * 68 + h * 8 + 4];
            float sc = q0.x * k0.x + q0.y * k0.y + q0.z * k0.z + q0.w * k0.w
                     + q1.x * k1.x + q1.y * k1.y + q1.z * k1.z + q1.w * k1.w;
            float p = __expf(sc * inv_sqrt_d - mx);
            denom += p;
            float4 v0 = *(const float4*)&s_v[k * 68 + h * 8];
            float4 v1 = *(const float4*)&s_v[k * 68 + h * 8 + 4];
            ac0.x += p * v0.x; ac0.y += p * v0.y; ac0.z += p * v0.z; ac0.w += p * v0.w;
            ac1.x += p * v1.x; ac1.y += p * v1.y; ac1.z += p * v1.z; ac1.w += p * v1.w;
        }
        float rinv = 1.f / denom;
        s_ao[ql * 65 + h * 8 + 0] = ac0.x * rinv;
        s_ao[ql * 65 + h * 8 + 1] = ac0.y * rinv;
        s_ao[ql * 65 + h * 8 + 2] = ac0.z * rinv;
        s_ao[ql * 65 + h * 8 + 3] = ac0.w * rinv;
        s_ao[ql * 65 + h * 8 + 4] = ac1.x * rinv;
        s_ao[ql * 65 + h * 8 + 5] = ac1.y * rinv;
        s_ao[ql * 65 + h * 8 + 6] = ac1.z * rinv;
        s_ao[ql * 65 + h * 8 + 7] = ac1.w * rinv;
    }
    __syncthreads();

    {
        const float4* bopv = (const float4*)bop;
        int nl = tid >> 4, e4 = tid & 15;
        float4 acc = bopv[e4];
        #pragma unroll 8
        for (int f = 0; f < 64; f++) {
            float av = s_ao[nl * 65 + f];
            acc.x += av * s_wop[(4 * e4 + 0) * 64 + f];
            acc.y += av * s_wop[(4 * e4 + 1) * 64 + f];
            acc.z += av * s_wop[(4 * e4 + 2) * 64 + f];
            acc.w += av * s_wop[(4 * e4 + 3) * 64 + f];
        }
        *(float4*)&out[(size_t)(B_SZ * 4096) + (size_t)b * 4096 + (r0 + nl) * 64 + 4 * e4] = acc;
    }
}

// ---------------- launch ----------------
extern "C" void kernel_launch(void* const* d_in, const int* in_sizes, int n_in,
                              void* d_out, int out_size) {
    const float* x   = (const float*)d_in[0];
    const float* EE  = (const float*)d_in[1];
    const float* w1  = (const float*)d_in[2];
    const float* b1  = (const float*)d_in[3];
    const float* w2  = (const float*)d_in[4];
    const float* b2  = (const float*)d_in[5];
    const float* Wip = (const float*)d_in[6];
    const float* bip = (const float*)d_in[7];
    const float* Wop = (const float*)d_in[8];
    const float* bop = (const float*)d_in[9];
    float* out = (float*)d_out;

    cudaFuncSetAttribute(fft_hilbert_kernel,
                         cudaFuncAttributeMaxDynamicSharedMemorySize, 65536);
    cudaFuncSetAttribute(gram_mma_kernel,
                         cudaFuncAttributeMaxDynamicSharedMemorySize, GRAM_SMEM);
    cudaFuncSetAttribute(tail1_kernel,
                         cudaFuncAttributeMaxDynamicSharedMemorySize, T1_FLOATS * 4);
    cudaFuncSetAttribute(tail2_kernel,
                         cudaFuncAttributeMaxDynamicSharedMemorySize, T2_FLOATS * 4);
    cudaFuncSetAttribute(tail3_kernel,
                         cudaFuncAttributeMaxDynamicSharedMemorySize, T3_FLOATS * 4);

    init_kernel<<<32, 256>>>(EE, w1);
    fft_hilbert_kernel<<<B_SZ * C_SZ / 2, 512, 65536>>>(x);
    gram_mma_kernel<<<dim3(KSPLIT, B_SZ), 256, GRAM_SMEM>>>();
    tail1_kernel<<<dim3(4, B_SZ), 256, T1_FLOATS * 4>>>(b1, w2, out);
    tail2_kernel<<<dim3(4, B_SZ), 256, T2_FLOATS * 4>>>(b2, Wip, bip, out);
    tail3_kernel<<<dim3(4, B_SZ), 256, T3_FLOATS * 4>>>(Wop, bop, out);
}